// round 10
// baseline (speedup 1.0000x reference)
#include <cuda_runtime.h>
#include <math.h>
#include <stdint.h>

#define BATCH 64
#define SEQ   512
#define EMB   256
#define HID   512
#define G4    2048   // 4*HID
#define NCLS  4
#define NCTA  64     // persistent CTAs (latency-optimized, half the SMs)
#define UNITS 8      // hidden units per CTA (NCTA*UNITS = HID)
#define WROWS 32     // 4 gates * UNITS
#define NGRP  8      // barrier groups (8 CTAs each)
#define HPAD  68     // fp32 pad stride
#define WPAD  516    // W_s row stride (floats)

// Scratch (allocation-free rule: __device__ globals)
__device__ float g_xg[(size_t)SEQ * G4 * BATCH];   // [t][n][b], n = gate*H + j
__device__ float g_h[2][HID * BATCH];              // [buf][k][b], tf32-bit floats
__device__ unsigned int g_bar_grp[NGRP * 32];      // one line per group
__device__ unsigned int g_bar_root;
__device__ unsigned int g_epoch;

__device__ __forceinline__ float sigmoidf_(float x) {
    return 1.0f / (1.0f + __expf(-x));
}
__device__ __forceinline__ uint32_t f2tf32(float f) {
    uint32_t u;
    asm("cvt.rna.tf32.f32 %0, %1;" : "=r"(u) : "f"(f));
    return u;
}
__device__ __forceinline__ void mma_tf32(float& d0, float& d1, float& d2, float& d3,
                                         uint32_t a0, uint32_t a1, uint32_t a2, uint32_t a3,
                                         uint32_t b0, uint32_t b1) {
    asm volatile("mma.sync.aligned.m16n8k8.row.col.f32.tf32.tf32.f32 "
                 "{%0,%1,%2,%3}, {%4,%5,%6,%7}, {%8,%9}, {%0,%1,%2,%3};"
                 : "+f"(d0), "+f"(d1), "+f"(d2), "+f"(d3)
                 : "r"(a0), "r"(a1), "r"(a2), "r"(a3), "r"(b0), "r"(b1));
}

// cp.async.cg: 16B global->shared, L1-bypass.
__device__ __forceinline__ void cp_async16(void* smem_dst, const void* gmem_src) {
    unsigned saddr = (unsigned)__cvta_generic_to_shared(smem_dst);
    asm volatile("cp.async.cg.shared.global [%0], [%1], 16;"
                 :: "r"(saddr), "l"(gmem_src) : "memory");
}
__device__ __forceinline__ void cp_async_commit() {
    asm volatile("cp.async.commit_group;" ::: "memory");
}
template <int N>
__device__ __forceinline__ void cp_async_wait() {
    asm volatile("cp.async.wait_group %0;" :: "n"(N) : "memory");
}

__global__ void init_state() {
    int i = blockIdx.x * blockDim.x + threadIdx.x;
    g_h[0][i] = 0.0f;
    if (i < NGRP * 32) g_bar_grp[i] = 0u;
    if (i == 0) { g_bar_root = 0u; g_epoch = 0u; }
}

// ============================================================================
// xg_gemm (tf32 mma, R8-proven): xg[t][n][b] = emb[tok] @ W_ih^T + bias
// ============================================================================
__global__ void __launch_bounds__(256)
xg_gemm(const int* __restrict__ x, const float* __restrict__ emb,
        const float* __restrict__ W_ih,
        const float* __restrict__ b_ih, const float* __restrict__ b_hh) {
    __shared__ float As[32][HPAD];
    __shared__ float Bs[32][HPAD];
    __shared__ int   tok_s[64];
    __shared__ float sbias[64];

    const int t    = blockIdx.y;
    const int ncta = blockIdx.x * 64;
    const int tid  = threadIdx.x;
    const int warp = tid >> 5;
    const int lane = tid & 31;
    const int gid  = lane >> 2;
    const int tig  = lane & 3;
    const int wm   = warp & 3;
    const int wn   = warp >> 2;
    const int m0   = wm * 16;

    if (tid < 64) {
        tok_s[tid] = x[tid * SEQ + t];
        int n = ncta + tid;
        sbias[tid] = b_ih[n] + b_hh[n];
    }
    __syncthreads();

    const uint32_t* Asu = (const uint32_t*)As;
    const uint32_t* Bsu = (const uint32_t*)Bs;

    float d[4][4] = {};

    for (int kt = 0; kt < EMB; kt += 32) {
        #pragma unroll
        for (int jj = 0; jj < 2; jj++) {
            int idx = tid + jj * 256;
            int row = idx >> 3, qk = idx & 7;
            float4 av = *(const float4*)(emb + (size_t)tok_s[row] * EMB + kt + qk * 4);
            As[qk*4+0][row] = __uint_as_float(f2tf32(av.x));
            As[qk*4+1][row] = __uint_as_float(f2tf32(av.y));
            As[qk*4+2][row] = __uint_as_float(f2tf32(av.z));
            As[qk*4+3][row] = __uint_as_float(f2tf32(av.w));
            float4 bv = *(const float4*)(W_ih + (size_t)(ncta + row) * EMB + kt + qk * 4);
            Bs[qk*4+0][row] = __uint_as_float(f2tf32(bv.x));
            Bs[qk*4+1][row] = __uint_as_float(f2tf32(bv.y));
            Bs[qk*4+2][row] = __uint_as_float(f2tf32(bv.z));
            Bs[qk*4+3][row] = __uint_as_float(f2tf32(bv.w));
        }
        __syncthreads();

        #pragma unroll
        for (int s = 0; s < 4; s++) {
            const int k0 = s * 8;
            uint32_t a0 = Asu[(k0 + tig)     * HPAD + m0 + gid];
            uint32_t a1 = Asu[(k0 + tig)     * HPAD + m0 + gid + 8];
            uint32_t a2 = Asu[(k0 + tig + 4) * HPAD + m0 + gid];
            uint32_t a3 = Asu[(k0 + tig + 4) * HPAD + m0 + gid + 8];
            #pragma unroll
            for (int nt = 0; nt < 4; nt++) {
                const int n0 = wn * 32 + nt * 8;
                uint32_t b0 = Bsu[(k0 + tig)     * HPAD + n0 + gid];
                uint32_t b1 = Bsu[(k0 + tig + 4) * HPAD + n0 + gid];
                mma_tf32(d[nt][0], d[nt][1], d[nt][2], d[nt][3],
                         a0, a1, a2, a3, b0, b1);
            }
        }
        __syncthreads();
    }

    #pragma unroll
    for (int nt = 0; nt < 4; nt++) {
        const int na = wn * 32 + nt * 8 + 2 * tig;
        const int nb = na + 1;
        const int r0 = m0 + gid;
        const int r1 = r0 + 8;
        g_xg[((size_t)t * G4 + ncta + na) * BATCH + r0] = d[nt][0] + sbias[na];
        g_xg[((size_t)t * G4 + ncta + nb) * BATCH + r0] = d[nt][1] + sbias[nb];
        g_xg[((size_t)t * G4 + ncta + na) * BATCH + r1] = d[nt][2] + sbias[na];
        g_xg[((size_t)t * G4 + ncta + nb) * BATCH + r1] = d[nt][3] + sbias[nb];
    }
}

// ============================================================================
// Persistent recurrence, tf32 mma. 64 CTAs x 512 threads (16 warps), 8 units.
// Per step: D[64 b][32 n] = h[64][512] @ W_cta[32][512]^T; warp = wm(4) x wn(4),
// full K per warp (64 mma). 4-chunk cp.async pipeline. Two-level grid barrier.
// ============================================================================
__global__ void __launch_bounds__(512, 1)
lstm_persistent(const float* __restrict__ W_hh) {
    extern __shared__ float sm[];
    float* h_s = sm;                          // [512][HPAD] tf32 bits
    float* W_s = sm + HID * HPAD;             // [32][WPAD]  tf32 bits
    float* pre = W_s + WROWS * WPAD;          // [32 n][HPAD] fp32

    const int tid  = threadIdx.x;             // 512
    const int cta  = blockIdx.x;
    const int warp = tid >> 5;
    const int lane = tid & 31;
    const int gid  = lane >> 2;
    const int tig  = lane & 3;
    const int wm   = warp & 3;                // m0 = wm*16
    const int wn   = warp >> 2;               // n0 = wn*8 (0..3)
    const int m0   = wm * 16;
    const int n0   = wn * 8;
    const int j0   = cta * UNITS;

    // One-time: 32 W_hh rows -> smem as tf32. row n = g*8+u.
    #pragma unroll
    for (int row = 0; row < WROWS; row++) {
        int g = row >> 3, u = row & 7;
        W_s[row * WPAD + tid] = __uint_as_float(
            f2tf32(W_hh[(size_t)(g * HID + j0 + u) * HID + tid]));
    }
    float c_reg = 0.0f;
    __syncthreads();

    const uint32_t* Hsu = (const uint32_t*)h_s;
    const uint32_t* Wsu = (const uint32_t*)W_s;

    // epilogue identity: all 512 threads: b, unit (0..7)
    const int eb = tid & 63;
    const int eu = tid >> 6;

    for (int t = 0; t < SEQ; t++) {
        const int rb = t & 1;
        const float4* hsrc = (const float4*)g_h[rb];

        // Prefetch chunk 0 (128 k rows -> padded h_s rows).
        #pragma unroll
        for (int i = 0; i < 4; i++) {
            int p = tid + i * 512;            // piece 0..2047
            int krow = p >> 4, sub = p & 15;
            cp_async16(h_s + krow * HPAD + sub * 4, hsrc + p);
        }
        cp_async_commit();

        // Prefetch xg — overlaps chunk-0 copy.
        const float* xg = g_xg + ((size_t)t * G4 + j0 + eu) * BATCH + eb;
        float xi = __ldcg(xg + 0 * HID * BATCH);
        float xf = __ldcg(xg + 1 * HID * BATCH);
        float xG = __ldcg(xg + 2 * HID * BATCH);
        float xo = __ldcg(xg + 3 * HID * BATCH);

        float d0 = 0.f, d1 = 0.f, d2 = 0.f, d3 = 0.f;

        #pragma unroll
        for (int ci = 0; ci < 4; ci++) {
            if (ci < 3) {
                const int base = (ci + 1) * 2048;
                #pragma unroll
                for (int i = 0; i < 4; i++) {
                    int p = tid + i * 512;
                    int krow = ((base + p) >> 4), sub = p & 15;
                    cp_async16(h_s + krow * HPAD + sub * 4, hsrc + base + p);
                }
                cp_async_commit();
                cp_async_wait<1>();
            } else {
                cp_async_wait<0>();
            }
            __syncthreads();

            #pragma unroll
            for (int s = 0; s < 16; s++) {
                const int k0 = (ci * 16 + s) * 8;
                uint32_t a0 = Hsu[(k0 + tig)     * HPAD + m0 + gid];
                uint32_t a1 = Hsu[(k0 + tig)     * HPAD + m0 + gid + 8];
                uint32_t a2 = Hsu[(k0 + tig + 4) * HPAD + m0 + gid];
                uint32_t a3 = Hsu[(k0 + tig + 4) * HPAD + m0 + gid + 8];
                uint32_t b0 = Wsu[(n0 + gid) * WPAD + k0 + tig];
                uint32_t b1 = Wsu[(n0 + gid) * WPAD + k0 + tig + 4];
                mma_tf32(d0, d1, d2, d3, a0, a1, a2, a3, b0, b1);
            }
        }

        // Store D partials: pre[n][b].
        {
            const int na = n0 + 2 * tig;
            const int r0 = m0 + gid;
            pre[(na)     * HPAD + r0]     = d0;
            pre[(na + 1) * HPAD + r0]     = d1;
            pre[(na)     * HPAD + r0 + 8] = d2;
            pre[(na + 1) * HPAD + r0 + 8] = d3;
        }
        __syncthreads();

        // Elementwise update — all 512 threads (b, u).
        {
            const int b = eb, u = eu;
            float ai = pre[(0 * UNITS + u) * HPAD + b];
            float af = pre[(1 * UNITS + u) * HPAD + b];
            float ag = pre[(2 * UNITS + u) * HPAD + b];
            float ao = pre[(3 * UNITS + u) * HPAD + b];

            float gi = sigmoidf_(ai + xi);
            float gf = sigmoidf_(af + xf);
            float gG = tanhf   (ag + xG);
            float go = sigmoidf_(ao + xo);
            c_reg = gf * c_reg + gi * gG;
            float hv = go * tanhf(c_reg);

            __stcg(&g_h[rb ^ 1][(j0 + u) * BATCH + b],
                   __uint_as_float(f2tf32(hv)));
        }

        // Two-level grid barrier; fence + arrive by tid0 only (CG grid.sync pattern).
        __syncthreads();
        if (tid == 0) {
            __threadfence();
            const unsigned step = (unsigned)(t + 1);
            bool released = false;
            unsigned a = atomicAdd(&g_bar_grp[(cta >> 3) * 32], 1u) + 1u;
            if (a == step * 8u) {                       // group complete
                unsigned r = atomicAdd(&g_bar_root, 1u) + 1u;
                if (r == step * NGRP) {                 // all groups complete
                    asm volatile("st.release.gpu.global.u32 [%0], %1;"
                                 :: "l"(&g_epoch), "r"(step) : "memory");
                    released = true;
                }
            }
            if (!released) {
                unsigned v;
                do {
                    asm volatile("ld.acquire.gpu.global.u32 %0, [%1];"
                                 : "=r"(v) : "l"(&g_epoch) : "memory");
                } while (v < step);
            }
            __threadfence();
        }
        __syncthreads();
    }
}

// Final FC: warp per output element (64*4 = 256 warps = 32 blocks).
__global__ void fc_kernel(const float* __restrict__ W_fc, const float* __restrict__ b_fc,
                          float* __restrict__ out) {
    const int warp = (blockIdx.x * blockDim.x + threadIdx.x) >> 5;
    const int lane = threadIdx.x & 31;
    const int b = warp >> 2, c = warp & 3;
    const float* h0 = g_h[0];
    const float* w  = W_fc + c * HID;
    float acc = 0.f;
    #pragma unroll 4
    for (int k = lane; k < HID; k += 32)
        acc += h0[k * BATCH + b] * w[k];
    #pragma unroll
    for (int off = 16; off; off >>= 1)
        acc += __shfl_xor_sync(0xFFFFFFFFu, acc, off);
    if (lane == 0) out[b * NCLS + c] = acc + b_fc[c];
}

extern "C" void kernel_launch(void* const* d_in, const int* in_sizes, int n_in,
                              void* d_out, int out_size) {
    const int*   x    = (const int*)  d_in[0];
    const float* emb  = (const float*)d_in[1];
    const float* W_ih = (const float*)d_in[2];
    const float* W_hh = (const float*)d_in[3];
    const float* b_ih = (const float*)d_in[4];
    const float* b_hh = (const float*)d_in[5];
    const float* W_fc = (const float*)d_in[6];
    const float* b_fc = (const float*)d_in[7];
    float* out = (float*)d_out;

    const int smem_bytes = (HID * HPAD + WROWS * WPAD + WROWS * HPAD) * sizeof(float); // ~209 KiB
    cudaFuncSetAttribute(lstm_persistent,
                         cudaFuncAttributeMaxDynamicSharedMemorySize, smem_bytes);

    init_state<<<64, 512>>>();

    dim3 g1(G4 / 64, SEQ);   // 32 x 512 CTAs
    xg_gemm<<<g1, 256>>>(x, emb, W_ih, b_ih, b_hh);

    lstm_persistent<<<NCTA, 512, smem_bytes>>>(W_hh);

    fc_kernel<<<32, 256>>>(W_fc, b_fc, out);
}

// round 11
// speedup vs baseline: 1.3746x; 1.3746x over previous
#include <cuda_runtime.h>
#include <math.h>
#include <stdint.h>

#define BATCH 64
#define SEQ   512
#define EMB   256
#define HID   512
#define G4    2048   // 4*HID
#define NCLS  4
#define NCTA  128    // persistent CTAs: 64 j-groups x 2 batch-halves
#define UNITS 8      // hidden units per j-group
#define WROWS 32     // 4 gates * UNITS
#define NGRP  16     // barrier groups (8 CTAs each)
#define HPAD  68     // fp32 pad stride (xg_gemm)
#define HS    36     // h_s row stride (32 batch + 4 pad), 16B-aligned rows
#define PS    36     // pre row stride
#define WPAD  516    // W_s row stride (floats)

// Scratch (allocation-free rule: __device__ globals)
__device__ float g_xg[(size_t)SEQ * G4 * BATCH];   // [t][n][b], n = gate*H + j
__device__ float g_h[2][HID * BATCH];              // [buf][k][b], tf32-bit floats
__device__ unsigned int g_bar_grp[NGRP * 32];      // one 128B line per group
__device__ unsigned int g_bar_root;
__device__ unsigned int g_epoch;

__device__ __forceinline__ float sigmoidf_(float x) {
    return 1.0f / (1.0f + __expf(-x));
}
__device__ __forceinline__ uint32_t f2tf32(float f) {
    uint32_t u;
    asm("cvt.rna.tf32.f32 %0, %1;" : "=r"(u) : "f"(f));
    return u;
}
__device__ __forceinline__ void mma_tf32(float& d0, float& d1, float& d2, float& d3,
                                         uint32_t a0, uint32_t a1, uint32_t a2, uint32_t a3,
                                         uint32_t b0, uint32_t b1) {
    asm volatile("mma.sync.aligned.m16n8k8.row.col.f32.tf32.tf32.f32 "
                 "{%0,%1,%2,%3}, {%4,%5,%6,%7}, {%8,%9}, {%0,%1,%2,%3};"
                 : "+f"(d0), "+f"(d1), "+f"(d2), "+f"(d3)
                 : "r"(a0), "r"(a1), "r"(a2), "r"(a3), "r"(b0), "r"(b1));
}

// cp.async.cg: 16B global->shared, L1-bypass.
__device__ __forceinline__ void cp_async16(void* smem_dst, const void* gmem_src) {
    unsigned saddr = (unsigned)__cvta_generic_to_shared(smem_dst);
    asm volatile("cp.async.cg.shared.global [%0], [%1], 16;"
                 :: "r"(saddr), "l"(gmem_src) : "memory");
}
__device__ __forceinline__ void cp_async_commit() {
    asm volatile("cp.async.commit_group;" ::: "memory");
}
template <int N>
__device__ __forceinline__ void cp_async_wait() {
    asm volatile("cp.async.wait_group %0;" :: "n"(N) : "memory");
}

__global__ void init_state() {
    int i = blockIdx.x * blockDim.x + threadIdx.x;
    g_h[0][i] = 0.0f;
    if (i < NGRP * 32) g_bar_grp[i] = 0u;
    if (i == 0) { g_bar_root = 0u; g_epoch = 0u; }
}

// ============================================================================
// xg_gemm (tf32 mma, R8-proven): xg[t][n][b] = emb[tok] @ W_ih^T + bias
// ============================================================================
__global__ void __launch_bounds__(256)
xg_gemm(const int* __restrict__ x, const float* __restrict__ emb,
        const float* __restrict__ W_ih,
        const float* __restrict__ b_ih, const float* __restrict__ b_hh) {
    __shared__ float As[32][HPAD];
    __shared__ float Bs[32][HPAD];
    __shared__ int   tok_s[64];
    __shared__ float sbias[64];

    const int t    = blockIdx.y;
    const int ncta = blockIdx.x * 64;
    const int tid  = threadIdx.x;
    const int warp = tid >> 5;
    const int lane = tid & 31;
    const int gid  = lane >> 2;
    const int tig  = lane & 3;
    const int wm   = warp & 3;
    const int wn   = warp >> 2;
    const int m0   = wm * 16;

    if (tid < 64) {
        tok_s[tid] = x[tid * SEQ + t];
        int n = ncta + tid;
        sbias[tid] = b_ih[n] + b_hh[n];
    }
    __syncthreads();

    const uint32_t* Asu = (const uint32_t*)As;
    const uint32_t* Bsu = (const uint32_t*)Bs;

    float d[4][4] = {};

    for (int kt = 0; kt < EMB; kt += 32) {
        #pragma unroll
        for (int jj = 0; jj < 2; jj++) {
            int idx = tid + jj * 256;
            int row = idx >> 3, qk = idx & 7;
            float4 av = *(const float4*)(emb + (size_t)tok_s[row] * EMB + kt + qk * 4);
            As[qk*4+0][row] = __uint_as_float(f2tf32(av.x));
            As[qk*4+1][row] = __uint_as_float(f2tf32(av.y));
            As[qk*4+2][row] = __uint_as_float(f2tf32(av.z));
            As[qk*4+3][row] = __uint_as_float(f2tf32(av.w));
            float4 bv = *(const float4*)(W_ih + (size_t)(ncta + row) * EMB + kt + qk * 4);
            Bs[qk*4+0][row] = __uint_as_float(f2tf32(bv.x));
            Bs[qk*4+1][row] = __uint_as_float(f2tf32(bv.y));
            Bs[qk*4+2][row] = __uint_as_float(f2tf32(bv.z));
            Bs[qk*4+3][row] = __uint_as_float(f2tf32(bv.w));
        }
        __syncthreads();

        #pragma unroll
        for (int s = 0; s < 4; s++) {
            const int k0 = s * 8;
            uint32_t a0 = Asu[(k0 + tig)     * HPAD + m0 + gid];
            uint32_t a1 = Asu[(k0 + tig)     * HPAD + m0 + gid + 8];
            uint32_t a2 = Asu[(k0 + tig + 4) * HPAD + m0 + gid];
            uint32_t a3 = Asu[(k0 + tig + 4) * HPAD + m0 + gid + 8];
            #pragma unroll
            for (int nt = 0; nt < 4; nt++) {
                const int n0 = wn * 32 + nt * 8;
                uint32_t b0 = Bsu[(k0 + tig)     * HPAD + n0 + gid];
                uint32_t b1 = Bsu[(k0 + tig + 4) * HPAD + n0 + gid];
                mma_tf32(d[nt][0], d[nt][1], d[nt][2], d[nt][3],
                         a0, a1, a2, a3, b0, b1);
            }
        }
        __syncthreads();
    }

    #pragma unroll
    for (int nt = 0; nt < 4; nt++) {
        const int na = wn * 32 + nt * 8 + 2 * tig;
        const int nb = na + 1;
        const int r0 = m0 + gid;
        const int r1 = r0 + 8;
        g_xg[((size_t)t * G4 + ncta + na) * BATCH + r0] = d[nt][0] + sbias[na];
        g_xg[((size_t)t * G4 + ncta + nb) * BATCH + r0] = d[nt][1] + sbias[nb];
        g_xg[((size_t)t * G4 + ncta + na) * BATCH + r1] = d[nt][2] + sbias[na];
        g_xg[((size_t)t * G4 + ncta + nb) * BATCH + r1] = d[nt][3] + sbias[nb];
    }
}

// ============================================================================
// Persistent recurrence, tf32 mma. 128 CTAs x 512 threads (16 warps).
// CTA = (j-group of 8 units, batch-half of 32). Per step: D[32 b][32 n] =
// h[32][512] @ W[32][512]^T. Warp = wm(2) x wn(4) x kh(2); 8 mma/chunk,
// 32 mma/step (same as R8). 4-chunk cp.async pipeline on a 64KB h slice.
// Two-level grid barrier, fence by tid0 only.
// ============================================================================
__global__ void __launch_bounds__(512, 1)
lstm_persistent(const float* __restrict__ W_hh) {
    extern __shared__ float sm[];
    float* h_s = sm;                          // [512][HS] tf32 bits (32 b cols)
    float* W_s = sm + HID * HS;               // [32][WPAD] tf32 bits
    float* pre = W_s + WROWS * WPAD;          // [2 kh][32 n][PS] fp32

    const int tid  = threadIdx.x;             // 512
    const int cta  = blockIdx.x;
    const int jg   = cta >> 1;                // j-group 0..63
    const int bh   = cta & 1;                 // batch half
    const int warp = tid >> 5;
    const int lane = tid & 31;
    const int gid  = lane >> 2;
    const int tig  = lane & 3;
    const int wm   = warp & 1;                // m0 = wm*16 (local batch)
    const int wn   = (warp >> 1) & 3;         // n0 = wn*8
    const int kh   = warp >> 3;               // split-K half (256 k each)
    const int m0   = wm * 16;
    const int n0   = wn * 8;
    const int j0   = jg * UNITS;
    const int b0g  = bh * 32;

    // One-time: 32 W_hh rows -> smem as tf32. row = g*8+u.
    #pragma unroll
    for (int row = 0; row < WROWS; row++) {
        int g = row >> 3, u = row & 7;
        W_s[row * WPAD + tid] = __uint_as_float(
            f2tf32(W_hh[(size_t)(g * HID + j0 + u) * HID + tid]));
    }
    float c_reg = 0.0f;
    __syncthreads();

    const uint32_t* Hsu = (const uint32_t*)h_s;
    const uint32_t* Wsu = (const uint32_t*)W_s;

    // epilogue identity (tid<256): local batch, unit
    const int ebl = tid & 31;
    const int eu  = (tid >> 5) & 7;
    const int ebg = b0g + ebl;

    for (int t = 0; t < SEQ; t++) {
        const int rb = t & 1;
        const float4* hsrc4 = (const float4*)g_h[rb];

        // Prefetch chunk 0: rows [0,128), 8 x16B pieces per row, 1024 pieces.
        #pragma unroll
        for (int i = 0; i < 2; i++) {
            int p = tid + i * 512;
            int krow = p >> 3, sub = p & 7;
            cp_async16(h_s + krow * HS + sub * 4,
                       hsrc4 + krow * 16 + bh * 8 + sub);
        }
        cp_async_commit();

        // Prefetch xg — overlaps chunk-0 copy.
        float xi = 0.f, xf = 0.f, xG = 0.f, xo = 0.f;
        if (tid < 256) {
            const float* xg = g_xg + ((size_t)t * G4 + j0 + eu) * BATCH + ebg;
            xi = __ldcg(xg + 0 * HID * BATCH);
            xf = __ldcg(xg + 1 * HID * BATCH);
            xG = __ldcg(xg + 2 * HID * BATCH);
            xo = __ldcg(xg + 3 * HID * BATCH);
        }

        float d0 = 0.f, d1 = 0.f, d2 = 0.f, d3 = 0.f;

        #pragma unroll
        for (int ci = 0; ci < 4; ci++) {
            if (ci < 3) {
                const int rbase = (ci + 1) * 128;
                #pragma unroll
                for (int i = 0; i < 2; i++) {
                    int p = tid + i * 512;
                    int krow = rbase + (p >> 3), sub = p & 7;
                    cp_async16(h_s + krow * HS + sub * 4,
                               hsrc4 + krow * 16 + bh * 8 + sub);
                }
                cp_async_commit();
                cp_async_wait<1>();
            } else {
                cp_async_wait<0>();
            }
            __syncthreads();

            const int ks0 = ci * 16 + kh * 8;
            #pragma unroll
            for (int s = 0; s < 8; s++) {
                const int k0 = (ks0 + s) * 8;
                uint32_t a0 = Hsu[(k0 + tig)     * HS + m0 + gid];
                uint32_t a1 = Hsu[(k0 + tig)     * HS + m0 + gid + 8];
                uint32_t a2 = Hsu[(k0 + tig + 4) * HS + m0 + gid];
                uint32_t a3 = Hsu[(k0 + tig + 4) * HS + m0 + gid + 8];
                uint32_t b0 = Wsu[(n0 + gid) * WPAD + k0 + tig];
                uint32_t b1 = Wsu[(n0 + gid) * WPAD + k0 + tig + 4];
                mma_tf32(d0, d1, d2, d3, a0, a1, a2, a3, b0, b1);
            }
        }

        // Split-K partials: pre[kh*32 + n][local b].
        {
            const int na = n0 + 2 * tig;
            const int r0 = m0 + gid;
            pre[(kh * 32 + na)     * PS + r0]     = d0;
            pre[(kh * 32 + na + 1) * PS + r0]     = d1;
            pre[(kh * 32 + na)     * PS + r0 + 8] = d2;
            pre[(kh * 32 + na + 1) * PS + r0 + 8] = d3;
        }
        __syncthreads();

        if (tid < 256) {
            const int b = ebl, u = eu;
            float ai = pre[(0 * 8 + u) * PS + b] + pre[(32 + 0 * 8 + u) * PS + b];
            float af = pre[(1 * 8 + u) * PS + b] + pre[(32 + 1 * 8 + u) * PS + b];
            float ag = pre[(2 * 8 + u) * PS + b] + pre[(32 + 2 * 8 + u) * PS + b];
            float ao = pre[(3 * 8 + u) * PS + b] + pre[(32 + 3 * 8 + u) * PS + b];

            float gi = sigmoidf_(ai + xi);
            float gf = sigmoidf_(af + xf);
            float gG = tanhf   (ag + xG);
            float go = sigmoidf_(ao + xo);
            c_reg = gf * c_reg + gi * gG;
            float hv = go * tanhf(c_reg);

            __stcg(&g_h[rb ^ 1][(j0 + u) * BATCH + ebg],
                   __uint_as_float(f2tf32(hv)));
        }

        // Two-level grid barrier; fence + arrive by tid0 only.
        __syncthreads();
        if (tid == 0) {
            __threadfence();
            const unsigned step = (unsigned)(t + 1);
            bool released = false;
            unsigned a = atomicAdd(&g_bar_grp[(cta >> 3) * 32], 1u) + 1u;
            if (a == step * 8u) {                       // group complete
                unsigned r = atomicAdd(&g_bar_root, 1u) + 1u;
                if (r == step * NGRP) {                 // all groups complete
                    asm volatile("st.release.gpu.global.u32 [%0], %1;"
                                 :: "l"(&g_epoch), "r"(step) : "memory");
                    released = true;
                }
            }
            if (!released) {
                unsigned v;
                do {
                    asm volatile("ld.acquire.gpu.global.u32 %0, [%1];"
                                 : "=r"(v) : "l"(&g_epoch) : "memory");
                } while (v < step);
            }
            __threadfence();
        }
        __syncthreads();
    }
}

// Final FC: warp per output element (64*4 = 256 warps = 32 blocks).
__global__ void fc_kernel(const float* __restrict__ W_fc, const float* __restrict__ b_fc,
                          float* __restrict__ out) {
    const int warp = (blockIdx.x * blockDim.x + threadIdx.x) >> 5;
    const int lane = threadIdx.x & 31;
    const int b = warp >> 2, c = warp & 3;
    const float* h0 = g_h[0];
    const float* w  = W_fc + c * HID;
    float acc = 0.f;
    #pragma unroll 4
    for (int k = lane; k < HID; k += 32)
        acc += h0[k * BATCH + b] * w[k];
    #pragma unroll
    for (int off = 16; off; off >>= 1)
        acc += __shfl_xor_sync(0xFFFFFFFFu, acc, off);
    if (lane == 0) out[b * NCLS + c] = acc + b_fc[c];
}

extern "C" void kernel_launch(void* const* d_in, const int* in_sizes, int n_in,
                              void* d_out, int out_size) {
    const int*   x    = (const int*)  d_in[0];
    const float* emb  = (const float*)d_in[1];
    const float* W_ih = (const float*)d_in[2];
    const float* W_hh = (const float*)d_in[3];
    const float* b_ih = (const float*)d_in[4];
    const float* b_hh = (const float*)d_in[5];
    const float* W_fc = (const float*)d_in[6];
    const float* b_fc = (const float*)d_in[7];
    float* out = (float*)d_out;

    const int smem_bytes = (HID * HS + WROWS * WPAD + 2 * WROWS * PS) * sizeof(float); // ~147 KiB
    cudaFuncSetAttribute(lstm_persistent,
                         cudaFuncAttributeMaxDynamicSharedMemorySize, smem_bytes);

    init_state<<<64, 512>>>();

    dim3 g1(G4 / 64, SEQ);   // 32 x 512 CTAs
    xg_gemm<<<g1, 256>>>(x, emb, W_ih, b_ih, b_hh);

    lstm_persistent<<<NCTA, 512, smem_bytes>>>(W_hh);

    fc_kernel<<<32, 256>>>(W_fc, b_fc, out);
}

// round 12
// speedup vs baseline: 1.7647x; 1.2839x over previous
#include <cuda_runtime.h>
#include <math.h>
#include <stdint.h>

#define BATCH 64
#define SEQ   512
#define EMB   256
#define HID   512
#define G4    2048   // 4*HID
#define NCLS  4
#define NCTA  128    // persistent CTAs: 64 j-groups x 2 batch-halves
#define UNITS 8      // hidden units per j-group
#define NGRP  16     // barrier groups (8 CTAs each)
#define HPAD  68     // fp32 pad stride (xg_gemm)
#define HS    40     // h_s row stride (32 batch + 8 pad) -> conflict-free frags
#define PS    36     // pre row stride (32 + 4)

// Scratch (allocation-free rule: __device__ globals)
__device__ float g_xg[(size_t)SEQ * G4 * BATCH];   // [t][n][b], n = gate*H + j
__device__ float g_h[2][HID * BATCH];              // [buf][k][b], tf32-bit floats
__device__ unsigned int g_bar_grp[NGRP * 32];      // one 128B line per group
__device__ unsigned int g_bar_root;
__device__ unsigned int g_epoch;

__device__ __forceinline__ float sigmoidf_(float x) {
    return 1.0f / (1.0f + __expf(-x));
}
__device__ __forceinline__ uint32_t f2tf32(float f) {
    uint32_t u;
    asm("cvt.rna.tf32.f32 %0, %1;" : "=r"(u) : "f"(f));
    return u;
}
__device__ __forceinline__ void mma_tf32(float& d0, float& d1, float& d2, float& d3,
                                         uint32_t a0, uint32_t a1, uint32_t a2, uint32_t a3,
                                         uint32_t b0, uint32_t b1) {
    asm volatile("mma.sync.aligned.m16n8k8.row.col.f32.tf32.tf32.f32 "
                 "{%0,%1,%2,%3}, {%4,%5,%6,%7}, {%8,%9}, {%0,%1,%2,%3};"
                 : "+f"(d0), "+f"(d1), "+f"(d2), "+f"(d3)
                 : "r"(a0), "r"(a1), "r"(a2), "r"(a3), "r"(b0), "r"(b1));
}

// cp.async.cg: 16B global->shared, L1-bypass.
__device__ __forceinline__ void cp_async16(void* smem_dst, const void* gmem_src) {
    unsigned saddr = (unsigned)__cvta_generic_to_shared(smem_dst);
    asm volatile("cp.async.cg.shared.global [%0], [%1], 16;"
                 :: "r"(saddr), "l"(gmem_src) : "memory");
}
__device__ __forceinline__ void cp_async_commit() {
    asm volatile("cp.async.commit_group;" ::: "memory");
}
template <int N>
__device__ __forceinline__ void cp_async_wait() {
    asm volatile("cp.async.wait_group %0;" :: "n"(N) : "memory");
}

__global__ void init_state() {
    int i = blockIdx.x * blockDim.x + threadIdx.x;
    g_h[0][i] = 0.0f;
    if (i < NGRP * 32) g_bar_grp[i] = 0u;
    if (i == 0) { g_bar_root = 0u; g_epoch = 0u; }
}

// ============================================================================
// xg_gemm (tf32 mma, R8-proven): xg[t][n][b] = emb[tok] @ W_ih^T + bias
// ============================================================================
__global__ void __launch_bounds__(256)
xg_gemm(const int* __restrict__ x, const float* __restrict__ emb,
        const float* __restrict__ W_ih,
        const float* __restrict__ b_ih, const float* __restrict__ b_hh) {
    __shared__ float As[32][HPAD];
    __shared__ float Bs[32][HPAD];
    __shared__ int   tok_s[64];
    __shared__ float sbias[64];

    const int t    = blockIdx.y;
    const int ncta = blockIdx.x * 64;
    const int tid  = threadIdx.x;
    const int warp = tid >> 5;
    const int lane = tid & 31;
    const int gid  = lane >> 2;
    const int tig  = lane & 3;
    const int wm   = warp & 3;
    const int wn   = warp >> 2;
    const int m0   = wm * 16;

    if (tid < 64) {
        tok_s[tid] = x[tid * SEQ + t];
        int n = ncta + tid;
        sbias[tid] = b_ih[n] + b_hh[n];
    }
    __syncthreads();

    const uint32_t* Asu = (const uint32_t*)As;
    const uint32_t* Bsu = (const uint32_t*)Bs;

    float d[4][4] = {};

    for (int kt = 0; kt < EMB; kt += 32) {
        #pragma unroll
        for (int jj = 0; jj < 2; jj++) {
            int idx = tid + jj * 256;
            int row = idx >> 3, qk = idx & 7;
            float4 av = *(const float4*)(emb + (size_t)tok_s[row] * EMB + kt + qk * 4);
            As[qk*4+0][row] = __uint_as_float(f2tf32(av.x));
            As[qk*4+1][row] = __uint_as_float(f2tf32(av.y));
            As[qk*4+2][row] = __uint_as_float(f2tf32(av.z));
            As[qk*4+3][row] = __uint_as_float(f2tf32(av.w));
            float4 bv = *(const float4*)(W_ih + (size_t)(ncta + row) * EMB + kt + qk * 4);
            Bs[qk*4+0][row] = __uint_as_float(f2tf32(bv.x));
            Bs[qk*4+1][row] = __uint_as_float(f2tf32(bv.y));
            Bs[qk*4+2][row] = __uint_as_float(f2tf32(bv.z));
            Bs[qk*4+3][row] = __uint_as_float(f2tf32(bv.w));
        }
        __syncthreads();

        #pragma unroll
        for (int s = 0; s < 4; s++) {
            const int k0 = s * 8;
            uint32_t a0 = Asu[(k0 + tig)     * HPAD + m0 + gid];
            uint32_t a1 = Asu[(k0 + tig)     * HPAD + m0 + gid + 8];
            uint32_t a2 = Asu[(k0 + tig + 4) * HPAD + m0 + gid];
            uint32_t a3 = Asu[(k0 + tig + 4) * HPAD + m0 + gid + 8];
            #pragma unroll
            for (int nt = 0; nt < 4; nt++) {
                const int n0 = wn * 32 + nt * 8;
                uint32_t b0 = Bsu[(k0 + tig)     * HPAD + n0 + gid];
                uint32_t b1 = Bsu[(k0 + tig + 4) * HPAD + n0 + gid];
                mma_tf32(d[nt][0], d[nt][1], d[nt][2], d[nt][3],
                         a0, a1, a2, a3, b0, b1);
            }
        }
        __syncthreads();
    }

    #pragma unroll
    for (int nt = 0; nt < 4; nt++) {
        const int na = wn * 32 + nt * 8 + 2 * tig;
        const int nb = na + 1;
        const int r0 = m0 + gid;
        const int r1 = r0 + 8;
        g_xg[((size_t)t * G4 + ncta + na) * BATCH + r0] = d[nt][0] + sbias[na];
        g_xg[((size_t)t * G4 + ncta + nb) * BATCH + r0] = d[nt][1] + sbias[nb];
        g_xg[((size_t)t * G4 + ncta + na) * BATCH + r1] = d[nt][2] + sbias[na];
        g_xg[((size_t)t * G4 + ncta + nb) * BATCH + r1] = d[nt][3] + sbias[nb];
    }
}

// ============================================================================
// Persistent recurrence, tf32 mma, W-in-registers. 128 CTAs x 512 threads.
// CTA = (j-group of 8 units -> 32 gate rows, batch-half of 32).
// Per step: D[32 b][32 n] = h[32][512] @ W[32][512]^T.
// 16 warps = wm(2 m-tiles) x kh(8 k-splits of 64); each warp covers all 4
// n-tiles with persistent W fragments in registers (64 regs, loaded once).
// A(h) fragments read from smem exactly once chip-wide (zero duplication).
// Single-shot 64KB cp.async h copy; two-level grid barrier.
// ============================================================================
__global__ void __launch_bounds__(512, 1)
lstm_persistent(const float* __restrict__ W_hh) {
    extern __shared__ float sm[];
    float* h_s = sm;                     // [512][HS] tf32 bits (32 b + pad)
    float* pre = sm + HID * HS;          // [8*32][PS] fp32 split-K partials

    const int tid  = threadIdx.x;        // 512
    const int cta  = blockIdx.x;
    const int jg   = cta >> 1;           // j-group 0..63
    const int bh   = cta & 1;            // batch half
    const int warp = tid >> 5;
    const int lane = tid & 31;
    const int gid  = lane >> 2;
    const int tig  = lane & 3;
    const int wm   = warp & 1;           // m-tile: m0 = wm*16 (local batch)
    const int kh   = warp >> 1;          // k-split 0..7 (64 k each)
    const int m0   = wm * 16;
    const int j0   = jg * UNITS;
    const int b0g  = bh * 32;

    // One-time: W fragments -> registers. wreg[nt][ks][2]:
    // b0 = W[n=nt*8+gid][k0+tig], b1 = W[..][k0+tig+4], k0 = kh*64+ks*8.
    uint32_t wreg[4][8][2];
    {
        const int n = /*per nt below*/ 0; (void)n;
        #pragma unroll
        for (int nt = 0; nt < 4; nt++) {
            const int nn = nt * 8 + gid;
            const int g = nn >> 3, u = nn & 7;
            const float* wrow = W_hh + (size_t)(g * HID + j0 + u) * HID + kh * 64;
            #pragma unroll
            for (int ks = 0; ks < 8; ks++) {
                wreg[nt][ks][0] = f2tf32(wrow[ks * 8 + tig]);
                wreg[nt][ks][1] = f2tf32(wrow[ks * 8 + tig + 4]);
            }
        }
    }
    float c_reg = 0.0f;

    const uint32_t* Hsu = (const uint32_t*)h_s;
    // epilogue identity (tid<256): local batch, unit
    const int ebl = tid & 31;
    const int eu  = (tid >> 5) & 7;
    const int ebg = b0g + ebl;

    for (int t = 0; t < SEQ; t++) {
        const int rb = t & 1;
        const float* hsrc = g_h[rb];

        // Single-shot copy of the 32-batch slice: 512 rows x 128B.
        // 4096 x16B pieces / 512 threads = 8 each.
        #pragma unroll
        for (int i = 0; i < 8; i++) {
            int p = tid + i * 512;
            int krow = p >> 3, sub = p & 7;
            cp_async16(h_s + krow * HS + sub * 4,
                       hsrc + krow * BATCH + b0g + sub * 4);
        }
        cp_async_commit();

        // Prefetch xg — overlaps the copy.
        float xi = 0.f, xf = 0.f, xG = 0.f, xo = 0.f;
        if (tid < 256) {
            const float* xg = g_xg + ((size_t)t * G4 + j0 + eu) * BATCH + ebg;
            xi = __ldcg(xg + 0 * HID * BATCH);
            xf = __ldcg(xg + 1 * HID * BATCH);
            xG = __ldcg(xg + 2 * HID * BATCH);
            xo = __ldcg(xg + 3 * HID * BATCH);
        }

        cp_async_wait<0>();
        __syncthreads();

        float d[4][4] = {};
        #pragma unroll
        for (int ks = 0; ks < 8; ks++) {
            const int k0 = kh * 64 + ks * 8;
            uint32_t a0 = Hsu[(k0 + tig)     * HS + m0 + gid];
            uint32_t a1 = Hsu[(k0 + tig)     * HS + m0 + gid + 8];
            uint32_t a2 = Hsu[(k0 + tig + 4) * HS + m0 + gid];
            uint32_t a3 = Hsu[(k0 + tig + 4) * HS + m0 + gid + 8];
            #pragma unroll
            for (int nt = 0; nt < 4; nt++) {
                mma_tf32(d[nt][0], d[nt][1], d[nt][2], d[nt][3],
                         a0, a1, a2, a3, wreg[nt][ks][0], wreg[nt][ks][1]);
            }
        }

        // Split-K partials: pre[kh*32 + n][local m].
        #pragma unroll
        for (int nt = 0; nt < 4; nt++) {
            const int na = nt * 8 + 2 * tig;
            const int r0 = m0 + gid;
            pre[(kh * 32 + na)     * PS + r0]     = d[nt][0];
            pre[(kh * 32 + na + 1) * PS + r0]     = d[nt][1];
            pre[(kh * 32 + na)     * PS + r0 + 8] = d[nt][2];
            pre[(kh * 32 + na + 1) * PS + r0 + 8] = d[nt][3];
        }
        __syncthreads();

        if (tid < 256) {
            const int b = ebl, u = eu;
            float ai = 0.f, af = 0.f, ag = 0.f, ao = 0.f;
            #pragma unroll
            for (int q = 0; q < 8; q++) {
                ai += pre[(q * 32 + 0 * 8 + u) * PS + b];
                af += pre[(q * 32 + 1 * 8 + u) * PS + b];
                ag += pre[(q * 32 + 2 * 8 + u) * PS + b];
                ao += pre[(q * 32 + 3 * 8 + u) * PS + b];
            }

            float gi = sigmoidf_(ai + xi);
            float gf = sigmoidf_(af + xf);
            float gG = tanhf   (ag + xG);
            float go = sigmoidf_(ao + xo);
            c_reg = gf * c_reg + gi * gG;
            float hv = go * tanhf(c_reg);

            __stcg(&g_h[rb ^ 1][(j0 + u) * BATCH + ebg],
                   __uint_as_float(f2tf32(hv)));
        }

        // Two-level grid barrier; fence + arrive by tid0 only.
        __syncthreads();
        if (tid == 0) {
            __threadfence();
            const unsigned step = (unsigned)(t + 1);
            bool released = false;
            unsigned a = atomicAdd(&g_bar_grp[(cta >> 3) * 32], 1u) + 1u;
            if (a == step * 8u) {
                unsigned r = atomicAdd(&g_bar_root, 1u) + 1u;
                if (r == step * NGRP) {
                    asm volatile("st.release.gpu.global.u32 [%0], %1;"
                                 :: "l"(&g_epoch), "r"(step) : "memory");
                    released = true;
                }
            }
            if (!released) {
                unsigned v;
                do {
                    asm volatile("ld.acquire.gpu.global.u32 %0, [%1];"
                                 : "=r"(v) : "l"(&g_epoch) : "memory");
                } while (v < step);
            }
            __threadfence();
        }
        __syncthreads();
    }
}

// Final FC: warp per output element (64*4 = 256 warps = 32 blocks).
__global__ void fc_kernel(const float* __restrict__ W_fc, const float* __restrict__ b_fc,
                          float* __restrict__ out) {
    const int warp = (blockIdx.x * blockDim.x + threadIdx.x) >> 5;
    const int lane = threadIdx.x & 31;
    const int b = warp >> 2, c = warp & 3;
    const float* h0 = g_h[0];
    const float* w  = W_fc + c * HID;
    float acc = 0.f;
    #pragma unroll 4
    for (int k = lane; k < HID; k += 32)
        acc += h0[k * BATCH + b] * w[k];
    #pragma unroll
    for (int off = 16; off; off >>= 1)
        acc += __shfl_xor_sync(0xFFFFFFFFu, acc, off);
    if (lane == 0) out[b * NCLS + c] = acc + b_fc[c];
}

extern "C" void kernel_launch(void* const* d_in, const int* in_sizes, int n_in,
                              void* d_out, int out_size) {
    const int*   x    = (const int*)  d_in[0];
    const float* emb  = (const float*)d_in[1];
    const float* W_ih = (const float*)d_in[2];
    const float* W_hh = (const float*)d_in[3];
    const float* b_ih = (const float*)d_in[4];
    const float* b_hh = (const float*)d_in[5];
    const float* W_fc = (const float*)d_in[6];
    const float* b_fc = (const float*)d_in[7];
    float* out = (float*)d_out;

    const int smem_bytes = (HID * HS + 8 * 32 * PS) * sizeof(float); // ~116 KiB
    cudaFuncSetAttribute(lstm_persistent,
                         cudaFuncAttributeMaxDynamicSharedMemorySize, smem_bytes);

    init_state<<<64, 512>>>();

    dim3 g1(G4 / 64, SEQ);   // 32 x 512 CTAs
    xg_gemm<<<g1, 256>>>(x, emb, W_ih, b_ih, b_hh);

    lstm_persistent<<<NCTA, 512, smem_bytes>>>(W_hh);

    fc_kernel<<<32, 256>>>(W_fc, b_fc, out);
}

// round 13
// speedup vs baseline: 1.9901x; 1.1277x over previous
#include <cuda_runtime.h>
#include <math.h>
#include <stdint.h>

#define BATCH 64
#define SEQ   512
#define EMB   256
#define HID   512
#define G4    2048   // 4*HID
#define NCLS  4
#define NCTA  128    // persistent CTAs: 64 j-groups x 2 batch-halves
#define UNITS 8      // hidden units per j-group
#define HPAD  68     // fp32 pad stride (xg_gemm)
#define HS    40     // h_s row stride (32 batch + 8 pad) -> conflict-free frags
#define PS    36     // pre row stride (32 + 4)

// Scratch (allocation-free rule: __device__ globals)
__device__ float g_xg[(size_t)SEQ * G4 * BATCH];   // [t][n][b], n = gate*H + j
__device__ float g_h[2][HID * BATCH];              // [buf][k][b], tf32-bit floats
// Barriers: 2 independent domains (one per batch-half), 8 groups of 8 each.
__device__ unsigned int g_bar_grp[16 * 32];        // one 128B line per group
__device__ unsigned int g_bar_root[2 * 32];
__device__ unsigned int g_epoch[2 * 32];

__device__ __forceinline__ float sigmoidf_(float x) {
    return 1.0f / (1.0f + __expf(-x));
}
__device__ __forceinline__ uint32_t f2tf32(float f) {
    uint32_t u;
    asm("cvt.rna.tf32.f32 %0, %1;" : "=r"(u) : "f"(f));
    return u;
}
__device__ __forceinline__ void mma_tf32(float& d0, float& d1, float& d2, float& d3,
                                         uint32_t a0, uint32_t a1, uint32_t a2, uint32_t a3,
                                         uint32_t b0, uint32_t b1) {
    asm volatile("mma.sync.aligned.m16n8k8.row.col.f32.tf32.tf32.f32 "
                 "{%0,%1,%2,%3}, {%4,%5,%6,%7}, {%8,%9}, {%0,%1,%2,%3};"
                 : "+f"(d0), "+f"(d1), "+f"(d2), "+f"(d3)
                 : "r"(a0), "r"(a1), "r"(a2), "r"(a3), "r"(b0), "r"(b1));
}

// cp.async.cg: 16B global->shared, L1-bypass.
__device__ __forceinline__ void cp_async16(void* smem_dst, const void* gmem_src) {
    unsigned saddr = (unsigned)__cvta_generic_to_shared(smem_dst);
    asm volatile("cp.async.cg.shared.global [%0], [%1], 16;"
                 :: "r"(saddr), "l"(gmem_src) : "memory");
}
__device__ __forceinline__ void cp_async_commit() {
    asm volatile("cp.async.commit_group;" ::: "memory");
}
template <int N>
__device__ __forceinline__ void cp_async_wait() {
    asm volatile("cp.async.wait_group %0;" :: "n"(N) : "memory");
}

__global__ void init_state() {
    int i = blockIdx.x * blockDim.x + threadIdx.x;
    g_h[0][i] = 0.0f;
    if (i < 16 * 32) g_bar_grp[i] = 0u;
    if (i < 2 * 32)  { g_bar_root[i] = 0u; g_epoch[i] = 0u; }
}

// ============================================================================
// xg_gemm (tf32 mma, R8-proven): xg[t][n][b] = emb[tok] @ W_ih^T + bias
// ============================================================================
__global__ void __launch_bounds__(256)
xg_gemm(const int* __restrict__ x, const float* __restrict__ emb,
        const float* __restrict__ W_ih,
        const float* __restrict__ b_ih, const float* __restrict__ b_hh) {
    __shared__ float As[32][HPAD];
    __shared__ float Bs[32][HPAD];
    __shared__ int   tok_s[64];
    __shared__ float sbias[64];

    const int t    = blockIdx.y;
    const int ncta = blockIdx.x * 64;
    const int tid  = threadIdx.x;
    const int warp = tid >> 5;
    const int lane = tid & 31;
    const int gid  = lane >> 2;
    const int tig  = lane & 3;
    const int wm   = warp & 3;
    const int wn   = warp >> 2;
    const int m0   = wm * 16;

    if (tid < 64) {
        tok_s[tid] = x[tid * SEQ + t];
        int n = ncta + tid;
        sbias[tid] = b_ih[n] + b_hh[n];
    }
    __syncthreads();

    const uint32_t* Asu = (const uint32_t*)As;
    const uint32_t* Bsu = (const uint32_t*)Bs;

    float d[4][4] = {};

    for (int kt = 0; kt < EMB; kt += 32) {
        #pragma unroll
        for (int jj = 0; jj < 2; jj++) {
            int idx = tid + jj * 256;
            int row = idx >> 3, qk = idx & 7;
            float4 av = *(const float4*)(emb + (size_t)tok_s[row] * EMB + kt + qk * 4);
            As[qk*4+0][row] = __uint_as_float(f2tf32(av.x));
            As[qk*4+1][row] = __uint_as_float(f2tf32(av.y));
            As[qk*4+2][row] = __uint_as_float(f2tf32(av.z));
            As[qk*4+3][row] = __uint_as_float(f2tf32(av.w));
            float4 bv = *(const float4*)(W_ih + (size_t)(ncta + row) * EMB + kt + qk * 4);
            Bs[qk*4+0][row] = __uint_as_float(f2tf32(bv.x));
            Bs[qk*4+1][row] = __uint_as_float(f2tf32(bv.y));
            Bs[qk*4+2][row] = __uint_as_float(f2tf32(bv.z));
            Bs[qk*4+3][row] = __uint_as_float(f2tf32(bv.w));
        }
        __syncthreads();

        #pragma unroll
        for (int s = 0; s < 4; s++) {
            const int k0 = s * 8;
            uint32_t a0 = Asu[(k0 + tig)     * HPAD + m0 + gid];
            uint32_t a1 = Asu[(k0 + tig)     * HPAD + m0 + gid + 8];
            uint32_t a2 = Asu[(k0 + tig + 4) * HPAD + m0 + gid];
            uint32_t a3 = Asu[(k0 + tig + 4) * HPAD + m0 + gid + 8];
            #pragma unroll
            for (int nt = 0; nt < 4; nt++) {
                const int n0 = wn * 32 + nt * 8;
                uint32_t b0 = Bsu[(k0 + tig)     * HPAD + n0 + gid];
                uint32_t b1 = Bsu[(k0 + tig + 4) * HPAD + n0 + gid];
                mma_tf32(d[nt][0], d[nt][1], d[nt][2], d[nt][3],
                         a0, a1, a2, a3, b0, b1);
            }
        }
        __syncthreads();
    }

    #pragma unroll
    for (int nt = 0; nt < 4; nt++) {
        const int na = wn * 32 + nt * 8 + 2 * tig;
        const int nb = na + 1;
        const int r0 = m0 + gid;
        const int r1 = r0 + 8;
        g_xg[((size_t)t * G4 + ncta + na) * BATCH + r0] = d[nt][0] + sbias[na];
        g_xg[((size_t)t * G4 + ncta + nb) * BATCH + r0] = d[nt][1] + sbias[nb];
        g_xg[((size_t)t * G4 + ncta + na) * BATCH + r1] = d[nt][2] + sbias[na];
        g_xg[((size_t)t * G4 + ncta + nb) * BATCH + r1] = d[nt][3] + sbias[nb];
    }
}

// ============================================================================
// Persistent recurrence, tf32 mma, W-in-registers (R12 structure).
// New in R13: per-warp-pair h copy (named barrier sync), dual barrier domains
// keyed by batch-half (64 CTAs each), skip barrier on last step.
// ============================================================================
__global__ void __launch_bounds__(512, 1)
lstm_persistent(const float* __restrict__ W_hh) {
    extern __shared__ float sm[];
    float* h_s = sm;                     // [512][HS] tf32 bits (32 b + pad)
    float* pre = sm + HID * HS;          // [8*32][PS] fp32 split-K partials

    const int tid  = threadIdx.x;        // 512
    const int cta  = blockIdx.x;
    const int jg   = cta >> 1;           // j-group 0..63
    const int bh   = cta & 1;            // batch half == barrier domain
    const int warp = tid >> 5;
    const int lane = tid & 31;
    const int gid  = lane >> 2;
    const int tig  = lane & 3;
    const int wm   = warp & 1;           // m-tile: m0 = wm*16 (local batch)
    const int kh   = warp >> 1;          // k-split 0..7 (64 k each)
    const int m0   = wm * 16;
    const int j0   = jg * UNITS;
    const int b0g  = bh * 32;

    // One-time: W fragments -> registers (64 regs), per warp's kh range.
    uint32_t wreg[4][8][2];
    #pragma unroll
    for (int nt = 0; nt < 4; nt++) {
        const int nn = nt * 8 + gid;
        const int g = nn >> 3, u = nn & 7;
        const float* wrow = W_hh + (size_t)(g * HID + j0 + u) * HID + kh * 64;
        #pragma unroll
        for (int ks = 0; ks < 8; ks++) {
            wreg[nt][ks][0] = f2tf32(wrow[ks * 8 + tig]);
            wreg[nt][ks][1] = f2tf32(wrow[ks * 8 + tig + 4]);
        }
    }
    float c_reg = 0.0f;

    const uint32_t* Hsu = (const uint32_t*)h_s;
    // epilogue identity (tid<256): local batch (lane), unit (warp)
    const int ebl = tid & 31;
    const int eu  = (tid >> 5) & 7;
    const int ebg = b0g + ebl;

    // This warp's copy slice: 32 k-rows starting at krow0 (its own mma range).
    const int krow0 = kh * 64 + wm * 32;

    for (int t = 0; t < SEQ; t++) {
        const int rb = t & 1;
        const float* hsrc = g_h[rb];

        // Per-warp copy: 32 rows x 128B = 256 x16B pieces / 32 lanes = 8 each.
        #pragma unroll
        for (int i = 0; i < 8; i++) {
            int p = lane + i * 32;
            int row = krow0 + (p >> 3), sub = p & 7;
            cp_async16(h_s + row * HS + sub * 4,
                       hsrc + row * BATCH + b0g + sub * 4);
        }
        cp_async_commit();

        // Prefetch xg — overlaps the copy.
        float xi = 0.f, xf = 0.f, xG = 0.f, xo = 0.f;
        if (tid < 256) {
            const float* xg = g_xg + ((size_t)t * G4 + j0 + eu) * BATCH + ebg;
            xi = __ldcg(xg + 0 * HID * BATCH);
            xf = __ldcg(xg + 1 * HID * BATCH);
            xG = __ldcg(xg + 2 * HID * BATCH);
            xo = __ldcg(xg + 3 * HID * BATCH);
        }

        cp_async_wait<0>();
        // Sync only with the wm-partner warp sharing this kh range.
        asm volatile("bar.sync %0, 64;" :: "r"(1 + kh) : "memory");

        float d[4][4] = {};
        #pragma unroll
        for (int ks = 0; ks < 8; ks++) {
            const int k0 = kh * 64 + ks * 8;
            uint32_t a0 = Hsu[(k0 + tig)     * HS + m0 + gid];
            uint32_t a1 = Hsu[(k0 + tig)     * HS + m0 + gid + 8];
            uint32_t a2 = Hsu[(k0 + tig + 4) * HS + m0 + gid];
            uint32_t a3 = Hsu[(k0 + tig + 4) * HS + m0 + gid + 8];
            #pragma unroll
            for (int nt = 0; nt < 4; nt++) {
                mma_tf32(d[nt][0], d[nt][1], d[nt][2], d[nt][3],
                         a0, a1, a2, a3, wreg[nt][ks][0], wreg[nt][ks][1]);
            }
        }

        // Split-K partials: pre[kh*32 + n][local m].
        #pragma unroll
        for (int nt = 0; nt < 4; nt++) {
            const int na = nt * 8 + 2 * tig;
            const int r0 = m0 + gid;
            pre[(kh * 32 + na)     * PS + r0]     = d[nt][0];
            pre[(kh * 32 + na + 1) * PS + r0]     = d[nt][1];
            pre[(kh * 32 + na)     * PS + r0 + 8] = d[nt][2];
            pre[(kh * 32 + na + 1) * PS + r0 + 8] = d[nt][3];
        }
        __syncthreads();

        if (tid < 256) {
            const int b = ebl, u = eu;
            float ai = 0.f, af = 0.f, ag = 0.f, ao = 0.f;
            #pragma unroll
            for (int q = 0; q < 8; q++) {
                ai += pre[(q * 32 + 0 * 8 + u) * PS + b];
                af += pre[(q * 32 + 1 * 8 + u) * PS + b];
                ag += pre[(q * 32 + 2 * 8 + u) * PS + b];
                ao += pre[(q * 32 + 3 * 8 + u) * PS + b];
            }

            float gi = sigmoidf_(ai + xi);
            float gf = sigmoidf_(af + xf);
            float gG = tanhf   (ag + xG);
            float go = sigmoidf_(ao + xo);
            c_reg = gf * c_reg + gi * gG;
            float hv = go * tanhf(c_reg);

            __stcg(&g_h[rb ^ 1][(j0 + u) * BATCH + ebg],
                   __uint_as_float(f2tf32(hv)));
        }

        // Dual-domain two-level grid barrier; fence + arrive by tid0 only.
        // Domain = batch half: CTA (jg,bh) depends only on CTAs (*,bh).
        __syncthreads();
        if (t < SEQ - 1) {
            if (tid == 0) {
                __threadfence();
                const unsigned step = (unsigned)(t + 1);
                const int grp = (bh << 3) + (jg >> 3);      // 8 groups/domain
                bool released = false;
                unsigned a = atomicAdd(&g_bar_grp[grp * 32], 1u) + 1u;
                if (a == step * 8u) {                       // group complete
                    unsigned r = atomicAdd(&g_bar_root[bh * 32], 1u) + 1u;
                    if (r == step * 8u) {                   // domain complete
                        asm volatile("st.release.gpu.global.u32 [%0], %1;"
                                     :: "l"(&g_epoch[bh * 32]), "r"(step) : "memory");
                        released = true;
                    }
                }
                if (!released) {
                    unsigned v;
                    do {
                        asm volatile("ld.acquire.gpu.global.u32 %0, [%1];"
                                     : "=r"(v) : "l"(&g_epoch[bh * 32]) : "memory");
                    } while (v < step);
                }
                __threadfence();
            }
            __syncthreads();
        }
    }
}

// Final FC: warp per output element (64*4 = 256 warps = 32 blocks).
__global__ void fc_kernel(const float* __restrict__ W_fc, const float* __restrict__ b_fc,
                          float* __restrict__ out) {
    const int warp = (blockIdx.x * blockDim.x + threadIdx.x) >> 5;
    const int lane = threadIdx.x & 31;
    const int b = warp >> 2, c = warp & 3;
    const float* h0 = g_h[0];
    const float* w  = W_fc + c * HID;
    float acc = 0.f;
    #pragma unroll 4
    for (int k = lane; k < HID; k += 32)
        acc += h0[k * BATCH + b] * w[k];
    #pragma unroll
    for (int off = 16; off; off >>= 1)
        acc += __shfl_xor_sync(0xFFFFFFFFu, acc, off);
    if (lane == 0) out[b * NCLS + c] = acc + b_fc[c];
}

extern "C" void kernel_launch(void* const* d_in, const int* in_sizes, int n_in,
                              void* d_out, int out_size) {
    const int*   x    = (const int*)  d_in[0];
    const float* emb  = (const float*)d_in[1];
    const float* W_ih = (const float*)d_in[2];
    const float* W_hh = (const float*)d_in[3];
    const float* b_ih = (const float*)d_in[4];
    const float* b_hh = (const float*)d_in[5];
    const float* W_fc = (const float*)d_in[6];
    const float* b_fc = (const float*)d_in[7];
    float* out = (float*)d_out;

    const int smem_bytes = (HID * HS + 8 * 32 * PS) * sizeof(float); // ~116 KiB
    cudaFuncSetAttribute(lstm_persistent,
                         cudaFuncAttributeMaxDynamicSharedMemorySize, smem_bytes);

    init_state<<<64, 512>>>();

    dim3 g1(G4 / 64, SEQ);   // 32 x 512 CTAs
    xg_gemm<<<g1, 256>>>(x, emb, W_ih, b_ih, b_hh);

    lstm_persistent<<<NCTA, 512, smem_bytes>>>(W_hh);

    fc_kernel<<<32, 256>>>(W_fc, b_fc, out);
}

// round 14
// speedup vs baseline: 2.5945x; 1.3037x over previous
#include <cuda_runtime.h>
#include <math.h>
#include <stdint.h>

#define BATCH 64
#define SEQ   512
#define EMB   256
#define HID   512
#define G4    2048   // 4*HID
#define NCLS  4
#define NCTA  128    // persistent CTAs: 64 j-groups x 2 batch-halves
#define UNITS 8      // hidden units per j-group
#define HPAD  68     // fp32 pad stride (xg_gemm)
#define HS    40     // h_s row stride (32 batch + 8 pad) -> conflict-free frags
#define PS    36     // pre row stride (32 + 4)

// Scratch (allocation-free rule: __device__ globals)
__device__ float g_xg[(size_t)SEQ * G4 * BATCH];   // [t][n][b], n = gate*H + j
__device__ float g_h[2][HID * BATCH];              // [buf][k][b], tf32-bit floats
// Producer-group flags: flag[bh][grp], grp = jg>>3 (8 producer CTAs each).
// Consumer warp (domain bh, k-split kh) polls flag[bh][kh] >= 8*t.
__device__ unsigned int g_flag[16 * 32];           // one 128B line per flag

__device__ __forceinline__ float sigmoidf_(float x) {
    return 1.0f / (1.0f + __expf(-x));
}
__device__ __forceinline__ uint32_t f2tf32(float f) {
    uint32_t u;
    asm("cvt.rna.tf32.f32 %0, %1;" : "=r"(u) : "f"(f));
    return u;
}
__device__ __forceinline__ void mma_tf32(float& d0, float& d1, float& d2, float& d3,
                                         uint32_t a0, uint32_t a1, uint32_t a2, uint32_t a3,
                                         uint32_t b0, uint32_t b1) {
    asm volatile("mma.sync.aligned.m16n8k8.row.col.f32.tf32.tf32.f32 "
                 "{%0,%1,%2,%3}, {%4,%5,%6,%7}, {%8,%9}, {%0,%1,%2,%3};"
                 : "+f"(d0), "+f"(d1), "+f"(d2), "+f"(d3)
                 : "r"(a0), "r"(a1), "r"(a2), "r"(a3), "r"(b0), "r"(b1));
}

// cp.async.cg: 16B global->shared, L1-bypass.
__device__ __forceinline__ void cp_async16(void* smem_dst, const void* gmem_src) {
    unsigned saddr = (unsigned)__cvta_generic_to_shared(smem_dst);
    asm volatile("cp.async.cg.shared.global [%0], [%1], 16;"
                 :: "r"(saddr), "l"(gmem_src) : "memory");
}
__device__ __forceinline__ void cp_async_commit() {
    asm volatile("cp.async.commit_group;" ::: "memory");
}
template <int N>
__device__ __forceinline__ void cp_async_wait() {
    asm volatile("cp.async.wait_group %0;" :: "n"(N) : "memory");
}

__global__ void init_state() {
    int i = blockIdx.x * blockDim.x + threadIdx.x;
    g_h[0][i] = 0.0f;
    if (i < 16 * 32) g_flag[i] = 0u;
}

// ============================================================================
// xg_gemm (tf32 mma, R8-proven): xg[t][n][b] = emb[tok] @ W_ih^T + bias
// ============================================================================
__global__ void __launch_bounds__(256)
xg_gemm(const int* __restrict__ x, const float* __restrict__ emb,
        const float* __restrict__ W_ih,
        const float* __restrict__ b_ih, const float* __restrict__ b_hh) {
    __shared__ float As[32][HPAD];
    __shared__ float Bs[32][HPAD];
    __shared__ int   tok_s[64];
    __shared__ float sbias[64];

    const int t    = blockIdx.y;
    const int ncta = blockIdx.x * 64;
    const int tid  = threadIdx.x;
    const int warp = tid >> 5;
    const int lane = tid & 31;
    const int gid  = lane >> 2;
    const int tig  = lane & 3;
    const int wm   = warp & 3;
    const int wn   = warp >> 2;
    const int m0   = wm * 16;

    if (tid < 64) {
        tok_s[tid] = x[tid * SEQ + t];
        int n = ncta + tid;
        sbias[tid] = b_ih[n] + b_hh[n];
    }
    __syncthreads();

    const uint32_t* Asu = (const uint32_t*)As;
    const uint32_t* Bsu = (const uint32_t*)Bs;

    float d[4][4] = {};

    for (int kt = 0; kt < EMB; kt += 32) {
        #pragma unroll
        for (int jj = 0; jj < 2; jj++) {
            int idx = tid + jj * 256;
            int row = idx >> 3, qk = idx & 7;
            float4 av = *(const float4*)(emb + (size_t)tok_s[row] * EMB + kt + qk * 4);
            As[qk*4+0][row] = __uint_as_float(f2tf32(av.x));
            As[qk*4+1][row] = __uint_as_float(f2tf32(av.y));
            As[qk*4+2][row] = __uint_as_float(f2tf32(av.z));
            As[qk*4+3][row] = __uint_as_float(f2tf32(av.w));
            float4 bv = *(const float4*)(W_ih + (size_t)(ncta + row) * EMB + kt + qk * 4);
            Bs[qk*4+0][row] = __uint_as_float(f2tf32(bv.x));
            Bs[qk*4+1][row] = __uint_as_float(f2tf32(bv.y));
            Bs[qk*4+2][row] = __uint_as_float(f2tf32(bv.z));
            Bs[qk*4+3][row] = __uint_as_float(f2tf32(bv.w));
        }
        __syncthreads();

        #pragma unroll
        for (int s = 0; s < 4; s++) {
            const int k0 = s * 8;
            uint32_t a0 = Asu[(k0 + tig)     * HPAD + m0 + gid];
            uint32_t a1 = Asu[(k0 + tig)     * HPAD + m0 + gid + 8];
            uint32_t a2 = Asu[(k0 + tig + 4) * HPAD + m0 + gid];
            uint32_t a3 = Asu[(k0 + tig + 4) * HPAD + m0 + gid + 8];
            #pragma unroll
            for (int nt = 0; nt < 4; nt++) {
                const int n0 = wn * 32 + nt * 8;
                uint32_t b0 = Bsu[(k0 + tig)     * HPAD + n0 + gid];
                uint32_t b1 = Bsu[(k0 + tig + 4) * HPAD + n0 + gid];
                mma_tf32(d[nt][0], d[nt][1], d[nt][2], d[nt][3],
                         a0, a1, a2, a3, b0, b1);
            }
        }
        __syncthreads();
    }

    #pragma unroll
    for (int nt = 0; nt < 4; nt++) {
        const int na = wn * 32 + nt * 8 + 2 * tig;
        const int nb = na + 1;
        const int r0 = m0 + gid;
        const int r1 = r0 + 8;
        g_xg[((size_t)t * G4 + ncta + na) * BATCH + r0] = d[nt][0] + sbias[na];
        g_xg[((size_t)t * G4 + ncta + nb) * BATCH + r0] = d[nt][1] + sbias[nb];
        g_xg[((size_t)t * G4 + ncta + na) * BATCH + r1] = d[nt][2] + sbias[na];
        g_xg[((size_t)t * G4 + ncta + nb) * BATCH + r1] = d[nt][3] + sbias[nb];
    }
}

// ============================================================================
// Persistent recurrence, tf32 mma, W-in-registers (R13 structure).
// New in R14: NO global barrier. Dataflow sync via producer-group flags:
// consumer warp (wm,kh) needs only h rows [kh*64,(kh+1)*64), produced by the
// 8 CTAs jg in [kh*8,kh*8+8) of its own batch-half domain. Each warp polls
// its single flag, copies its slice, syncs with its wm-partner, computes.
// ============================================================================
__global__ void __launch_bounds__(512, 1)
lstm_persistent(const float* __restrict__ W_hh) {
    extern __shared__ float sm[];
    float* h_s = sm;                     // [512][HS] tf32 bits (32 b + pad)
    float* pre = sm + HID * HS;          // [8*32][PS] fp32 split-K partials

    const int tid  = threadIdx.x;        // 512
    const int cta  = blockIdx.x;
    const int jg   = cta >> 1;           // j-group 0..63
    const int bh   = cta & 1;            // batch half == flag domain
    const int warp = tid >> 5;
    const int lane = tid & 31;
    const int gid  = lane >> 2;
    const int tig  = lane & 3;
    const int wm   = warp & 1;           // m-tile: m0 = wm*16 (local batch)
    const int kh   = warp >> 1;          // k-split 0..7 (64 k each)
    const int m0   = wm * 16;
    const int j0   = jg * UNITS;
    const int b0g  = bh * 32;

    // Flag addresses: this warp's consumer flag, this CTA's producer flag.
    unsigned int* my_cons_flag = &g_flag[(bh * 8 + kh) * 32];
    unsigned int* my_prod_flag = &g_flag[(bh * 8 + (jg >> 3)) * 32];

    // One-time: W fragments -> registers (64 regs), per warp's kh range.
    uint32_t wreg[4][8][2];
    #pragma unroll
    for (int nt = 0; nt < 4; nt++) {
        const int nn = nt * 8 + gid;
        const int g = nn >> 3, u = nn & 7;
        const float* wrow = W_hh + (size_t)(g * HID + j0 + u) * HID + kh * 64;
        #pragma unroll
        for (int ks = 0; ks < 8; ks++) {
            wreg[nt][ks][0] = f2tf32(wrow[ks * 8 + tig]);
            wreg[nt][ks][1] = f2tf32(wrow[ks * 8 + tig + 4]);
        }
    }
    float c_reg = 0.0f;

    const uint32_t* Hsu = (const uint32_t*)h_s;
    // epilogue identity (tid<256): local batch (lane), unit (warp)
    const int ebl = tid & 31;
    const int eu  = (tid >> 5) & 7;
    const int ebg = b0g + ebl;

    // This warp's copy slice: 32 k-rows starting at krow0 (its own mma range).
    const int krow0 = kh * 64 + wm * 32;

    for (int t = 0; t < SEQ; t++) {
        const int rb = t & 1;
        const float* hsrc = g_h[rb];

        // Dataflow wait: this warp's producer group must have finished step t-1.
        if (t > 0) {
            const unsigned tgt = 8u * (unsigned)t;
            unsigned v;
            do {
                asm volatile("ld.acquire.gpu.global.u32 %0, [%1];"
                             : "=r"(v) : "l"(my_cons_flag) : "memory");
            } while (v < tgt);
        }

        // Per-warp copy: 32 rows x 128B = 256 x16B pieces / 32 lanes = 8 each.
        #pragma unroll
        for (int i = 0; i < 8; i++) {
            int p = lane + i * 32;
            int row = krow0 + (p >> 3), sub = p & 7;
            cp_async16(h_s + row * HS + sub * 4,
                       hsrc + row * BATCH + b0g + sub * 4);
        }
        cp_async_commit();

        // Prefetch xg — overlaps the copy.
        float xi = 0.f, xf = 0.f, xG = 0.f, xo = 0.f;
        if (tid < 256) {
            const float* xg = g_xg + ((size_t)t * G4 + j0 + eu) * BATCH + ebg;
            xi = __ldcg(xg + 0 * HID * BATCH);
            xf = __ldcg(xg + 1 * HID * BATCH);
            xG = __ldcg(xg + 2 * HID * BATCH);
            xo = __ldcg(xg + 3 * HID * BATCH);
        }

        cp_async_wait<0>();
        // Sync only with the wm-partner warp sharing this kh range.
        asm volatile("bar.sync %0, 64;" :: "r"(1 + kh) : "memory");

        float d[4][4] = {};
        #pragma unroll
        for (int ks = 0; ks < 8; ks++) {
            const int k0 = kh * 64 + ks * 8;
            uint32_t a0 = Hsu[(k0 + tig)     * HS + m0 + gid];
            uint32_t a1 = Hsu[(k0 + tig)     * HS + m0 + gid + 8];
            uint32_t a2 = Hsu[(k0 + tig + 4) * HS + m0 + gid];
            uint32_t a3 = Hsu[(k0 + tig + 4) * HS + m0 + gid + 8];
            #pragma unroll
            for (int nt = 0; nt < 4; nt++) {
                mma_tf32(d[nt][0], d[nt][1], d[nt][2], d[nt][3],
                         a0, a1, a2, a3, wreg[nt][ks][0], wreg[nt][ks][1]);
            }
        }

        // Split-K partials: pre[kh*32 + n][local m].
        #pragma unroll
        for (int nt = 0; nt < 4; nt++) {
            const int na = nt * 8 + 2 * tig;
            const int r0 = m0 + gid;
            pre[(kh * 32 + na)     * PS + r0]     = d[nt][0];
            pre[(kh * 32 + na + 1) * PS + r0]     = d[nt][1];
            pre[(kh * 32 + na)     * PS + r0 + 8] = d[nt][2];
            pre[(kh * 32 + na + 1) * PS + r0 + 8] = d[nt][3];
        }
        __syncthreads();

        if (tid < 256) {
            const int b = ebl, u = eu;
            float ai = 0.f, af = 0.f, ag = 0.f, ao = 0.f;
            #pragma unroll
            for (int q = 0; q < 8; q++) {
                ai += pre[(q * 32 + 0 * 8 + u) * PS + b];
                af += pre[(q * 32 + 1 * 8 + u) * PS + b];
                ag += pre[(q * 32 + 2 * 8 + u) * PS + b];
                ao += pre[(q * 32 + 3 * 8 + u) * PS + b];
            }

            float gi = sigmoidf_(ai + xi);
            float gf = sigmoidf_(af + xf);
            float gG = tanhf   (ag + xG);
            float go = sigmoidf_(ao + xo);
            c_reg = gf * c_reg + gi * gG;
            float hv = go * tanhf(c_reg);

            __stcg(&g_h[rb ^ 1][(j0 + u) * BATCH + ebg],
                   __uint_as_float(f2tf32(hv)));
        }

        // Orders: all warps' mma/epilogue done before (a) producer arrive,
        // (b) next step's h_s/pre overwrite.
        __syncthreads();

        // Producer arrive: h(t+1) for this CTA's 8 rows is published.
        if (t < SEQ - 1 && tid == 0) {
            __threadfence();
            asm volatile("red.release.gpu.global.add.u32 [%0], 1;"
                         :: "l"(my_prod_flag) : "memory");
        }
    }
}

// Final FC: warp per output element (64*4 = 256 warps = 32 blocks).
__global__ void fc_kernel(const float* __restrict__ W_fc, const float* __restrict__ b_fc,
                          float* __restrict__ out) {
    const int warp = (blockIdx.x * blockDim.x + threadIdx.x) >> 5;
    const int lane = threadIdx.x & 31;
    const int b = warp >> 2, c = warp & 3;
    const float* h0 = g_h[0];
    const float* w  = W_fc + c * HID;
    float acc = 0.f;
    #pragma unroll 4
    for (int k = lane; k < HID; k += 32)
        acc += h0[k * BATCH + b] * w[k];
    #pragma unroll
    for (int off = 16; off; off >>= 1)
        acc += __shfl_xor_sync(0xFFFFFFFFu, acc, off);
    if (lane == 0) out[b * NCLS + c] = acc + b_fc[c];
}

extern "C" void kernel_launch(void* const* d_in, const int* in_sizes, int n_in,
                              void* d_out, int out_size) {
    const int*   x    = (const int*)  d_in[0];
    const float* emb  = (const float*)d_in[1];
    const float* W_ih = (const float*)d_in[2];
    const float* W_hh = (const float*)d_in[3];
    const float* b_ih = (const float*)d_in[4];
    const float* b_hh = (const float*)d_in[5];
    const float* W_fc = (const float*)d_in[6];
    const float* b_fc = (const float*)d_in[7];
    float* out = (float*)d_out;

    const int smem_bytes = (HID * HS + 8 * 32 * PS) * sizeof(float); // ~116 KiB
    cudaFuncSetAttribute(lstm_persistent,
                         cudaFuncAttributeMaxDynamicSharedMemorySize, smem_bytes);

    init_state<<<64, 512>>>();

    dim3 g1(G4 / 64, SEQ);   // 32 x 512 CTAs
    xg_gemm<<<g1, 256>>>(x, emb, W_ih, b_ih, b_hh);

    lstm_persistent<<<NCTA, 512, smem_bytes>>>(W_hh);

    fc_kernel<<<32, 256>>>(W_fc, b_fc, out);
}